// round 5
// baseline (speedup 1.0000x reference)
#include <cuda_runtime.h>
#include <stdint.h>

// Problem constants (fixed shapes)
#define M_NODES   131072
#define K_DIM     256
#define N_PROJ    256
#define NUM_G     256
#define NPG       512          // nodes per graph
#define NUM_Q     256

// Scratch (device globals; no allocation allowed in kernel_launch)
__device__ float g_xT [(size_t)K_DIM * M_NODES];       // x transposed: [k][node]      (134 MB)
__device__ float g_xpt[(size_t)NUM_G * N_PROJ * NPG];  // xp transposed: [g][p][i]     (134 MB)

// ---------------------------------------------------------------------------
// Kernel 1: transpose x [M,K] -> g_xT [K,M]  (coalesced both sides)
// ---------------------------------------------------------------------------
__global__ void transpose_kernel(const float* __restrict__ x) {
    __shared__ float tile[32][33];
    int tx = threadIdx.x & 31;
    int ty = threadIdx.x >> 5;          // 0..7
    int m0 = blockIdx.x * 32;
    int k0 = blockIdx.y * 32;
#pragma unroll
    for (int i = 0; i < 32; i += 8)
        tile[ty + i][tx] = x[(size_t)(m0 + ty + i) * K_DIM + k0 + tx];
    __syncthreads();
#pragma unroll
    for (int i = 0; i < 32; i += 8)
        g_xT[(size_t)(k0 + ty + i) * M_NODES + m0 + tx] = tile[tx][ty + i];
}

// ---------------------------------------------------------------------------
// Kernel 2: SGEMM via packed fma.rn.f32x2, output written transposed per graph
//   xp_t[(g*256 + j)*512 + i] = sum_k x[node][k] * proj[k][j],  node = g*512+i
// ---------------------------------------------------------------------------
#define GBM 256
#define GBN 64
#define GBK 32
#define GTHREADS 256
#define SMEM_A_FLOATS (GBK * GBM)   // 8192
#define SMEM_B_FLOATS (GBK * GBN)   // 2048
#define GEMM_SMEM_BYTES ((SMEM_A_FLOATS + SMEM_B_FLOATS) * 2 * 4)  // 81920

__device__ __forceinline__ void cp_async16(uint32_t saddr, const void* gptr) {
    asm volatile("cp.async.cg.shared.global [%0], [%1], 16;" :: "r"(saddr), "l"(gptr));
}
__device__ __forceinline__ void cp_commit() { asm volatile("cp.async.commit_group;"); }
__device__ __forceinline__ void cp_wait1() { asm volatile("cp.async.wait_group 1;"); }
__device__ __forceinline__ void cp_wait0() { asm volatile("cp.async.wait_group 0;"); }

__device__ __forceinline__ unsigned long long pk2(float lo, float hi) {
    unsigned long long r;
    asm("mov.b64 %0, {%1, %2};" : "=l"(r) : "f"(lo), "f"(hi));
    return r;
}
__device__ __forceinline__ void upk2(unsigned long long v, float& lo, float& hi) {
    asm("mov.b64 {%0, %1}, %2;" : "=f"(lo), "=f"(hi) : "l"(v));
}
__device__ __forceinline__ void ffma2(unsigned long long& d, unsigned long long a, unsigned long long b) {
    asm("fma.rn.f32x2 %0, %1, %2, %0;" : "+l"(d) : "l"(a), "l"(b));
}

__global__ void __launch_bounds__(GTHREADS, 2)
gemm_kernel(const float* __restrict__ proj) {
    extern __shared__ float smem[];
    float* As = smem;                          // [2][GBK][GBM]
    float* Bs = smem + 2 * SMEM_A_FLOATS;      // [2][GBK][GBN]

    const int t     = threadIdx.x;
    const int mBase = blockIdx.y * GBM;
    const int nBase = blockIdx.x * GBN;
    const int lane  = t & 31;
    const int w     = t >> 5;
    const int m0    = lane * 8;                // covers 0..255
    const int n0    = w * 8;                   // covers 0..63

    auto loadChunk = [&](int c, int buf) {
        const int kBase = c * GBK;
        uint32_t aB = (uint32_t)__cvta_generic_to_shared(As + buf * SMEM_A_FLOATS);
#pragma unroll
        for (int r = 0; r < 8; r++) {
            int u  = t + GTHREADS * r;        // 0..2047 16B units
            int kk = u >> 6;                  // /(GBM/4)
            int m4 = u & 63;
            cp_async16(aB + (uint32_t)(kk * GBM + m4 * 4) * 4,
                       g_xT + (size_t)(kBase + kk) * M_NODES + mBase + m4 * 4);
        }
        uint32_t bB = (uint32_t)__cvta_generic_to_shared(Bs + buf * SMEM_B_FLOATS);
#pragma unroll
        for (int r = 0; r < 2; r++) {
            int u  = t + GTHREADS * r;        // 0..511
            int kk = u >> 4;                  // /(GBN/4)
            int j4 = u & 15;
            cp_async16(bB + (uint32_t)(kk * GBN + j4 * 4) * 4,
                       proj + (size_t)(kBase + kk) * N_PROJ + nBase + j4 * 4);
        }
        cp_commit();
    };

    unsigned long long acc[8][4];
#pragma unroll
    for (int i = 0; i < 8; i++)
#pragma unroll
        for (int p = 0; p < 4; p++) acc[i][p] = 0ULL;

    loadChunk(0, 0);

    const int NCHUNK = K_DIM / GBK;            // 8
    for (int c = 0; c < NCHUNK; c++) {
        if (c + 1 < NCHUNK) { loadChunk(c + 1, (c + 1) & 1); cp_wait1(); }
        else                { cp_wait0(); }
        __syncthreads();

        const float* Ab = As + (c & 1) * SMEM_A_FLOATS;
        const float* Bb = Bs + (c & 1) * SMEM_B_FLOATS;

#pragma unroll 8
        for (int kk = 0; kk < GBK; kk++) {
            float4 a0 = *(const float4*)(Ab + kk * GBM + m0);
            float4 a1 = *(const float4*)(Ab + kk * GBM + m0 + 4);
            float4 b0 = *(const float4*)(Bb + kk * GBN + n0);
            float4 b1 = *(const float4*)(Bb + kk * GBN + n0 + 4);
            unsigned long long bp0 = pk2(b0.x, b0.y);
            unsigned long long bp1 = pk2(b0.z, b0.w);
            unsigned long long bp2 = pk2(b1.x, b1.y);
            unsigned long long bp3 = pk2(b1.z, b1.w);
            float am[8] = {a0.x, a0.y, a0.z, a0.w, a1.x, a1.y, a1.z, a1.w};
#pragma unroll
            for (int i = 0; i < 8; i++) {
                unsigned long long ap = pk2(am[i], am[i]);
                ffma2(acc[i][0], ap, bp0);
                ffma2(acc[i][1], ap, bp1);
                ffma2(acc[i][2], ap, bp2);
                ffma2(acc[i][3], ap, bp3);
            }
        }
        __syncthreads();
    }

    // Epilogue: write transposed. CTA's 256 m-rows live inside one graph half.
    const int g     = mBase >> 9;
    const int iBase = mBase & 511;             // 0 or 256
    const size_t colBase = ((size_t)g * N_PROJ + nBase) * NPG + iBase + m0;

#pragma unroll
    for (int p = 0; p < 4; p++) {
        float xs[8], ys[8];
#pragma unroll
        for (int i = 0; i < 8; i++) upk2(acc[i][p], xs[i], ys[i]);
        float* o0 = g_xpt + colBase + (size_t)(n0 + 2 * p) * NPG;
        float* o1 = o0 + NPG;
        *(float4*)(o0)     = make_float4(xs[0], xs[1], xs[2], xs[3]);
        *(float4*)(o0 + 4) = make_float4(xs[4], xs[5], xs[6], xs[7]);
        *(float4*)(o1)     = make_float4(ys[0], ys[1], ys[2], ys[3]);
        *(float4*)(o1 + 4) = make_float4(ys[4], ys[5], ys[6], ys[7]);
    }
}

// ---------------------------------------------------------------------------
// Kernel 3: per-warp bitonic sort of 512 values + quantile gather + write
// ---------------------------------------------------------------------------
template<int KK, int J>
__device__ __forceinline__ void bstep(float (&v)[16], int lane) {
    if constexpr (J >= 16) {
#pragma unroll
        for (int r = 0; r < 16; r++) {
            float pv = __shfl_xor_sync(0xffffffffu, v[r], J >> 4);
            int i = lane * 16 + r;
            bool takeMin = ((i & KK) == 0) == ((i & J) == 0);
            v[r] = takeMin ? fminf(v[r], pv) : fmaxf(v[r], pv);
        }
    } else {
#pragma unroll
        for (int r = 0; r < 16; r++) {
            if ((r & J) == 0) {
                int i = lane * 16 + r;
                bool up = ((i & KK) == 0);
                float a = v[r], b = v[r | J];
                float mn = fminf(a, b), mx = fmaxf(a, b);
                v[r]     = up ? mn : mx;
                v[r | J] = up ? mx : mn;
            }
        }
    }
}
template<int KK, int J>
__device__ __forceinline__ void bmerge(float (&v)[16], int lane) {
    bstep<KK, J>(v, lane);
    if constexpr (J > 1) bmerge<KK, J / 2>(v, lane);
}

__global__ void __launch_bounds__(256)
sort_quant_kernel(const float* __restrict__ cw, float* __restrict__ out) {
    __shared__ float sbuf[8][512];      // sorted columns, one per warp
    __shared__ float qbuf[8][264];      // quantiles staged (padded stride)
    __shared__ int   qidx[NUM_Q];

    const int t = threadIdx.x;
    qidx[t] = (int)floorf(cw[t] * (float)(NPG - 1));   // matches jnp.floor(cw*511)
    __syncthreads();

    const int w    = t >> 5;
    const int lane = t & 31;
    const int col  = blockIdx.x * 8 + w;               // (g,p) column id

    // Load 16 consecutive values per thread (element = lane*16 + r)
    float v[16];
    const float4* src = (const float4*)(g_xpt + (size_t)col * NPG);
#pragma unroll
    for (int q = 0; q < 4; q++) {
        float4 f = src[lane * 4 + q];
        v[q * 4 + 0] = f.x; v[q * 4 + 1] = f.y;
        v[q * 4 + 2] = f.z; v[q * 4 + 3] = f.w;
    }

    // Bitonic sort (ascending), 512 elements across the warp
    bmerge<2, 1>(v, lane);
    bmerge<4, 2>(v, lane);
    bmerge<8, 4>(v, lane);
    bmerge<16, 8>(v, lane);
    bmerge<32, 16>(v, lane);
    bmerge<64, 32>(v, lane);
    bmerge<128, 64>(v, lane);
    bmerge<256, 128>(v, lane);
    bmerge<512, 256>(v, lane);

    // Stage sorted column in smem (rank e at sbuf[w][e])
    float4* dst = (float4*)sbuf[w];
#pragma unroll
    for (int q = 0; q < 4; q++)
        dst[lane * 4 + q] = make_float4(v[q * 4 + 0], v[q * 4 + 1], v[q * 4 + 2], v[q * 4 + 3]);
    __syncwarp();

    // Gather quantiles, apply 1/scale = 1/256
#pragma unroll
    for (int s = 0; s < 8; s++) {
        int q = lane + 32 * s;
        qbuf[w][q] = sbuf[w][qidx[q]] * (1.0f / 256.0f);
    }
    __syncthreads();

    // Coalesced write: out[g*65536 + q*256 + p], 8 consecutive p per CTA
    const int gg    = blockIdx.x >> 5;
    const int pbase = (blockIdx.x * 8) & 255;
    const size_t obase = (size_t)gg * (NUM_Q * N_PROJ) + pbase;
#pragma unroll
    for (int s = 0; s < 8; s++) {
        int e  = t + 256 * s;          // 0..2047
        int q  = e >> 3;
        int wp = e & 7;
        out[obase + (size_t)q * N_PROJ + wp] = qbuf[wp][q];
    }
}

// ---------------------------------------------------------------------------
// kernel_launch: transpose -> gemm -> sort/quantile (graph-capturable)
// ---------------------------------------------------------------------------
extern "C" void kernel_launch(void* const* d_in, const int* in_sizes, int n_in,
                              void* d_out, int out_size) {
    const float* x    = (const float*)d_in[0];   // [131072, 256] f32
    const float* proj = (const float*)d_in[1];   // [256, 256]    f32
    const float* cw   = (const float*)d_in[2];   // [256]         f32
    float* out = (float*)d_out;                  // [256, 65536]  f32

    cudaFuncSetAttribute(gemm_kernel,
                         cudaFuncAttributeMaxDynamicSharedMemorySize,
                         GEMM_SMEM_BYTES);

    transpose_kernel<<<dim3(M_NODES / 32, K_DIM / 32), 256>>>(x);
    gemm_kernel<<<dim3(N_PROJ / GBN, M_NODES / GBM), GTHREADS, GEMM_SMEM_BYTES>>>(proj);
    sort_quant_kernel<<<(NUM_G * N_PROJ) / 8, 256>>>(cw, out);
}

// round 7
// speedup vs baseline: 1.4753x; 1.4753x over previous
#include <cuda_runtime.h>
#include <cuda_bf16.h>
#include <stdint.h>

// Problem constants (fixed shapes)
#define M_NODES   131072
#define K_DIM     256
#define N_PROJ    256
#define NUM_G     256
#define NPG       512          // nodes per graph
#define NUM_Q     256

// Scratch (device globals; no allocation allowed in kernel_launch)
__device__ __nv_bfloat16 g_xhi[(size_t)M_NODES * K_DIM];   // 64 MB
__device__ __nv_bfloat16 g_xlo[(size_t)M_NODES * K_DIM];   // 64 MB
__device__ __nv_bfloat16 g_bhi[N_PROJ * K_DIM];            // proj^T hi [n][k]
__device__ __nv_bfloat16 g_blo[N_PROJ * K_DIM];            // proj^T lo [n][k]
__device__ float g_xpt[(size_t)NUM_G * N_PROJ * NPG];      // xp transposed [g][p][i]

// ---------------------------------------------------------------------------
// PTX helpers (base ISA only — no sm_103a-gated features)
// ---------------------------------------------------------------------------
__device__ __forceinline__ uint32_t smem_u32(const void* p) {
    uint32_t a;
    asm("{ .reg .u64 t; cvta.to.shared.u64 t, %1; cvt.u32.u64 %0, t; }" : "=r"(a) : "l"(p));
    return a;
}
__device__ __forceinline__ void cp_async16(uint32_t saddr, const void* gptr) {
    asm volatile("cp.async.cg.shared.global [%0], [%1], 16;" :: "r"(saddr), "l"(gptr));
}
__device__ __forceinline__ void cp_commit() { asm volatile("cp.async.commit_group;"); }
__device__ __forceinline__ void cp_wait1()  { asm volatile("cp.async.wait_group 1;"); }
__device__ __forceinline__ void cp_wait0()  { asm volatile("cp.async.wait_group 0;"); }

__device__ __forceinline__ void ldsm4(uint32_t& r0, uint32_t& r1, uint32_t& r2, uint32_t& r3,
                                      uint32_t addr) {
    asm volatile("ldmatrix.sync.aligned.m8n8.x4.shared.b16 {%0,%1,%2,%3}, [%4];"
                 : "=r"(r0), "=r"(r1), "=r"(r2), "=r"(r3) : "r"(addr));
}
__device__ __forceinline__ void mma_bf16(float* c, const uint32_t* a, uint32_t b0, uint32_t b1) {
    asm volatile("mma.sync.aligned.m16n8k16.row.col.f32.bf16.bf16.f32 "
                 "{%0,%1,%2,%3}, {%4,%5,%6,%7}, {%8,%9}, {%0,%1,%2,%3};"
                 : "+f"(c[0]), "+f"(c[1]), "+f"(c[2]), "+f"(c[3])
                 : "r"(a[0]), "r"(a[1]), "r"(a[2]), "r"(a[3]), "r"(b0), "r"(b1));
}

// ---------------------------------------------------------------------------
// Kernel 1a: split-convert x (fp32 -> bf16 hi + bf16 lo), row-major [M,K]
// ---------------------------------------------------------------------------
__global__ void convx_kernel(const float* __restrict__ x) {
    size_t i = ((size_t)blockIdx.x * 256 + threadIdx.x) * 4;
    float4 v = *(const float4*)(x + i);
    float f[4] = {v.x, v.y, v.z, v.w};
    uint32_t hi[2], lo[2];
#pragma unroll
    for (int j = 0; j < 2; j++) {
        __nv_bfloat16 h0 = __float2bfloat16(f[2*j]);
        __nv_bfloat16 h1 = __float2bfloat16(f[2*j+1]);
        __nv_bfloat16 l0 = __float2bfloat16(f[2*j]   - __bfloat162float(h0));
        __nv_bfloat16 l1 = __float2bfloat16(f[2*j+1] - __bfloat162float(h1));
        hi[j] = (uint32_t)__bfloat16_as_ushort(h0) | ((uint32_t)__bfloat16_as_ushort(h1) << 16);
        lo[j] = (uint32_t)__bfloat16_as_ushort(l0) | ((uint32_t)__bfloat16_as_ushort(l1) << 16);
    }
    *(uint2*)(g_xhi + i) = make_uint2(hi[0], hi[1]);
    *(uint2*)(g_xlo + i) = make_uint2(lo[0], lo[1]);
}

// ---------------------------------------------------------------------------
// Kernel 1b: split-convert + transpose proj -> B[n][k] (K-major)
// ---------------------------------------------------------------------------
__global__ void convp_kernel(const float* __restrict__ proj) {
    int n = blockIdx.x, k = threadIdx.x;
    float v = proj[(size_t)k * N_PROJ + n];
    __nv_bfloat16 h = __float2bfloat16(v);
    __nv_bfloat16 l = __float2bfloat16(v - __bfloat162float(h));
    g_bhi[n * K_DIM + k] = h;
    g_blo[n * K_DIM + k] = l;
}

// ---------------------------------------------------------------------------
// Kernel 2: HMMA bf16-split GEMM (mma.sync m16n8k16), BM=128 BN=128 BK=32
//   3 passes per K-chunk: Ah*Bh + Ah*Bl + Al*Bh, fp32 accum in registers.
//   Epilogue writes transposed into g_xpt[g][p][i] (smem-staged, coalesced).
// ---------------------------------------------------------------------------
#define BM 128
#define BN 128
#define BK 32
#define GTHREADS 256
// smem per buffer: A 128 rows x 128B (hi segs 0..3, lo segs 4..7) = 16KB; B same
#define S_BUF    32768
#define S_BOFF   16384
#define EPI_PAD  132
#define GEMM_SMEM (BN * EPI_PAD * 4)   // 67584 > 2*S_BUF(65536)

__global__ void __launch_bounds__(GTHREADS, 2)
gemm_hmma_kernel() {
    extern __shared__ char smem[];
    const uint32_t sb = smem_u32(smem);

    const int t     = threadIdx.x;
    const int lane  = t & 31;
    const int wid   = t >> 5;
    const int mBase = blockIdx.y * BM;
    const int nBase = blockIdx.x * BN;
    const int wm    = (wid >> 2) * 64;   // warp tile 64 x 32
    const int wn    = (wid & 3) * 32;

    // ldmatrix per-lane geometry
    const int rsel  = lane & 15;          // row within 16-row ldsm tile
    const int khalf = lane >> 4;          // which 8-col half
    const int kx    = lane & 7;           // swizzle xor term (row & 7)

    // byte row offsets within tile for the 4 A m-subtiles and 2 B n-subtiles
    uint32_t mByte[4], nByte[2];
#pragma unroll
    for (int mi = 0; mi < 4; mi++) mByte[mi] = (uint32_t)(wm + mi * 16 + rsel) * 128;
#pragma unroll
    for (int ni = 0; ni < 2; ni++) nByte[ni] = (uint32_t)(wn + ni * 16 + rsel) * 128;

    auto loadChunk = [&](int c) {
        const int kB = c * BK;
        const uint32_t bufA = sb + (c & 1) * S_BUF;
        const uint32_t bufB = bufA + S_BOFF;
#pragma unroll
        for (int r = 0; r < 4; r++) {
            int u   = t + GTHREADS * r;          // 0..1023
            int row = u >> 3;
            int gg  = u & 7;                     // 0..3 hi, 4..7 lo
            uint32_t off = (uint32_t)(row * 128 + gg * 16);
            uint32_t sw  = off ^ ((off >> 3) & 0x70);
            int kOff = kB + (gg & 3) * 8;
            const __nv_bfloat16* asrc = (gg < 4 ? g_xhi : g_xlo)
                                      + (size_t)(mBase + row) * K_DIM + kOff;
            cp_async16(bufA + sw, asrc);
            const __nv_bfloat16* bsrc = (gg < 4 ? g_bhi : g_blo)
                                      + (size_t)(nBase + row) * K_DIM + kOff;
            cp_async16(bufB + sw, bsrc);
        }
        cp_commit();
    };

    float acc[4][4][4];
#pragma unroll
    for (int mi = 0; mi < 4; mi++)
#pragma unroll
        for (int ni = 0; ni < 4; ni++)
#pragma unroll
            for (int r = 0; r < 4; r++) acc[mi][ni][r] = 0.0f;

    loadChunk(0);
    loadChunk(1);

    const int NCH = K_DIM / BK;   // 8
    for (int c = 0; c < NCH; c++) {
        if (c == NCH - 1) cp_wait0(); else cp_wait1();
        __syncthreads();
        const uint32_t bufA = sb + (c & 1) * S_BUF;
        const uint32_t bufB = bufA + S_BOFF;

#pragma unroll
        for (int ks = 0; ks < 2; ks++) {
            // seg index: hi = ks*2 + khalf (0..3), lo = 4 + ...
            const uint32_t segH = (uint32_t)((ks * 2 + khalf) ^ kx) << 4;
            const uint32_t segLA = (uint32_t)((4 + ks * 2 + khalf) ^ kx) << 4;

            uint32_t ah[4][4], bh[2][4];
#pragma unroll
            for (int mi = 0; mi < 4; mi++)
                ldsm4(ah[mi][0], ah[mi][1], ah[mi][2], ah[mi][3], bufA + mByte[mi] + segH);
#pragma unroll
            for (int ni = 0; ni < 2; ni++)
                ldsm4(bh[ni][0], bh[ni][1], bh[ni][2], bh[ni][3], bufB + nByte[ni] + segH);

            // pass 1: Ah * Bh
#pragma unroll
            for (int mi = 0; mi < 4; mi++)
#pragma unroll
                for (int ni = 0; ni < 4; ni++)
                    mma_bf16(acc[mi][ni], ah[mi], bh[ni >> 1][ni & 1], bh[ni >> 1][(ni & 1) + 2]);

            // pass 2: Ah * Bl
            uint32_t bl[2][4];
#pragma unroll
            for (int ni = 0; ni < 2; ni++)
                ldsm4(bl[ni][0], bl[ni][1], bl[ni][2], bl[ni][3], bufB + nByte[ni] + segLA);
#pragma unroll
            for (int mi = 0; mi < 4; mi++)
#pragma unroll
                for (int ni = 0; ni < 4; ni++)
                    mma_bf16(acc[mi][ni], ah[mi], bl[ni >> 1][ni & 1], bl[ni >> 1][(ni & 1) + 2]);

            // pass 3: Al * Bh
            uint32_t al[4][4];
#pragma unroll
            for (int mi = 0; mi < 4; mi++)
                ldsm4(al[mi][0], al[mi][1], al[mi][2], al[mi][3], bufA + mByte[mi] + segLA);
#pragma unroll
            for (int mi = 0; mi < 4; mi++)
#pragma unroll
                for (int ni = 0; ni < 4; ni++)
                    mma_bf16(acc[mi][ni], al[mi], bh[ni >> 1][ni & 1], bh[ni >> 1][(ni & 1) + 2]);
        }

        __syncthreads();
        if (c + 2 < NCH) loadChunk(c + 2);
    }

    // Epilogue: stage D transposed in smem [n][m] (stride EPI_PAD -> conflict-free)
    float* sOut = (float*)smem;
    const int crow = lane >> 2;
    const int ccol = (lane & 3) * 2;
#pragma unroll
    for (int mi = 0; mi < 4; mi++)
#pragma unroll
        for (int ni = 0; ni < 4; ni++) {
            int m0 = wm + mi * 16 + crow;
            int n0 = wn + ni * 8 + ccol;
            sOut[(n0    ) * EPI_PAD + m0    ] = acc[mi][ni][0];
            sOut[(n0 + 1) * EPI_PAD + m0    ] = acc[mi][ni][1];
            sOut[(n0    ) * EPI_PAD + m0 + 8] = acc[mi][ni][2];
            sOut[(n0 + 1) * EPI_PAD + m0 + 8] = acc[mi][ni][3];
        }
    __syncthreads();

    // Coalesced global write: g_xpt[(g*256 + n)*512 + i]
    const int g     = mBase >> 9;
    const int iBase = mBase & 511;
#pragma unroll
    for (int r = 0; r < 16; r++) {
        int u   = t + GTHREADS * r;          // 0..4095
        int row = u >> 5;                    // n_local
        int pos = u & 31;                    // float4 within 128 m
        float4 v = *(float4*)&sOut[row * EPI_PAD + pos * 4];
        float* dst = g_xpt + ((size_t)(g * N_PROJ + nBase + row)) * NPG + iBase + pos * 4;
        *(float4*)dst = v;
    }
}

// ---------------------------------------------------------------------------
// Kernel 3: per-warp bitonic sort of 512 values + quantile gather + write
// ---------------------------------------------------------------------------
template<int KK, int J>
__device__ __forceinline__ void bstep(float (&v)[16], int lane) {
    if constexpr (J >= 16) {
#pragma unroll
        for (int r = 0; r < 16; r++) {
            float pv = __shfl_xor_sync(0xffffffffu, v[r], J >> 4);
            int i = lane * 16 + r;
            bool takeMin = ((i & KK) == 0) == ((i & J) == 0);
            v[r] = takeMin ? fminf(v[r], pv) : fmaxf(v[r], pv);
        }
    } else {
#pragma unroll
        for (int r = 0; r < 16; r++) {
            if ((r & J) == 0) {
                int i = lane * 16 + r;
                bool up = ((i & KK) == 0);
                float a = v[r], b = v[r | J];
                float mn = fminf(a, b), mx = fmaxf(a, b);
                v[r]     = up ? mn : mx;
                v[r | J] = up ? mx : mn;
            }
        }
    }
}
template<int KK, int J>
__device__ __forceinline__ void bmerge(float (&v)[16], int lane) {
    bstep<KK, J>(v, lane);
    if constexpr (J > 1) bmerge<KK, J / 2>(v, lane);
}

__global__ void __launch_bounds__(256)
sort_quant_kernel(const float* __restrict__ cw, float* __restrict__ out) {
    __shared__ float sbuf[8][512];      // sorted columns, one per warp
    __shared__ float qbuf[8][264];      // quantiles staged (padded stride)
    __shared__ int   qidx[NUM_Q];

    const int t = threadIdx.x;
    qidx[t] = (int)floorf(cw[t] * (float)(NPG - 1));   // matches jnp.floor(cw*511)
    __syncthreads();

    const int w    = t >> 5;
    const int lane = t & 31;
    const int col  = blockIdx.x * 8 + w;               // (g,p) column id

    float v[16];
    const float4* src = (const float4*)(g_xpt + (size_t)col * NPG);
#pragma unroll
    for (int q = 0; q < 4; q++) {
        float4 f = src[lane * 4 + q];
        v[q * 4 + 0] = f.x; v[q * 4 + 1] = f.y;
        v[q * 4 + 2] = f.z; v[q * 4 + 3] = f.w;
    }

    bmerge<2, 1>(v, lane);
    bmerge<4, 2>(v, lane);
    bmerge<8, 4>(v, lane);
    bmerge<16, 8>(v, lane);
    bmerge<32, 16>(v, lane);
    bmerge<64, 32>(v, lane);
    bmerge<128, 64>(v, lane);
    bmerge<256, 128>(v, lane);
    bmerge<512, 256>(v, lane);

    float4* dst = (float4*)sbuf[w];
#pragma unroll
    for (int q = 0; q < 4; q++)
        dst[lane * 4 + q] = make_float4(v[q * 4 + 0], v[q * 4 + 1], v[q * 4 + 2], v[q * 4 + 3]);
    __syncwarp();

#pragma unroll
    for (int s = 0; s < 8; s++) {
        int q = lane + 32 * s;
        qbuf[w][q] = sbuf[w][qidx[q]] * (1.0f / 256.0f);
    }
    __syncthreads();

    const int gg    = blockIdx.x >> 5;
    const int pbase = (blockIdx.x * 8) & 255;
    const size_t obase = (size_t)gg * (NUM_Q * N_PROJ) + pbase;
#pragma unroll
    for (int s = 0; s < 8; s++) {
        int e  = t + 256 * s;          // 0..2047
        int q  = e >> 3;
        int wp = e & 7;
        out[obase + (size_t)q * N_PROJ + wp] = qbuf[wp][q];
    }
}

// ---------------------------------------------------------------------------
// kernel_launch: convert -> HMMA gemm -> sort/quantile (graph-capturable)
// ---------------------------------------------------------------------------
extern "C" void kernel_launch(void* const* d_in, const int* in_sizes, int n_in,
                              void* d_out, int out_size) {
    const float* x    = (const float*)d_in[0];   // [131072, 256] f32
    const float* proj = (const float*)d_in[1];   // [256, 256]    f32
    const float* cw   = (const float*)d_in[2];   // [256]         f32
    float* out = (float*)d_out;                  // [256, 65536]  f32

    cudaFuncSetAttribute(gemm_hmma_kernel,
                         cudaFuncAttributeMaxDynamicSharedMemorySize,
                         GEMM_SMEM);

    convx_kernel<<<(M_NODES * K_DIM) / (256 * 4), 256>>>(x);
    convp_kernel<<<N_PROJ, K_DIM>>>(proj);
    gemm_hmma_kernel<<<dim3(N_PROJ / BN, M_NODES / BM), GTHREADS, GEMM_SMEM>>>();
    sort_quant_kernel<<<(NUM_G * N_PROJ) / 8, 256>>>(cw, out);
}

// round 8
// speedup vs baseline: 1.5967x; 1.0823x over previous
#include <cuda_runtime.h>
#include <cuda_bf16.h>
#include <stdint.h>

// Problem constants (fixed shapes)
#define M_NODES   131072
#define K_DIM     256
#define N_PROJ    256
#define NUM_G     256
#define NPG       512          // nodes per graph
#define NUM_Q     256

// Scratch (device globals; no allocation allowed in kernel_launch)
__device__ __nv_bfloat16 g_bhi[N_PROJ * K_DIM];            // proj^T hi [n][k]
__device__ __nv_bfloat16 g_blo[N_PROJ * K_DIM];            // proj^T lo [n][k]
__device__ float g_xpt[(size_t)NUM_G * N_PROJ * NPG];      // xp transposed [g][p][i]

// ---------------------------------------------------------------------------
// PTX helpers (base ISA only — no sm_103a-gated features)
// ---------------------------------------------------------------------------
__device__ __forceinline__ uint32_t smem_u32(const void* p) {
    uint32_t a;
    asm("{ .reg .u64 t; cvta.to.shared.u64 t, %1; cvt.u32.u64 %0, t; }" : "=r"(a) : "l"(p));
    return a;
}
__device__ __forceinline__ void cp_async16(uint32_t saddr, const void* gptr) {
    asm volatile("cp.async.cg.shared.global [%0], [%1], 16;" :: "r"(saddr), "l"(gptr));
}
__device__ __forceinline__ void cp_commit() { asm volatile("cp.async.commit_group;"); }
__device__ __forceinline__ void cp_wait1()  { asm volatile("cp.async.wait_group 1;"); }
__device__ __forceinline__ void cp_wait0()  { asm volatile("cp.async.wait_group 0;"); }

__device__ __forceinline__ void ldsm4(uint32_t& r0, uint32_t& r1, uint32_t& r2, uint32_t& r3,
                                      uint32_t addr) {
    asm volatile("ldmatrix.sync.aligned.m8n8.x4.shared.b16 {%0,%1,%2,%3}, [%4];"
                 : "=r"(r0), "=r"(r1), "=r"(r2), "=r"(r3) : "r"(addr));
}
__device__ __forceinline__ void mma_bf16(float* c, const uint32_t* a, uint32_t b0, uint32_t b1) {
    asm volatile("mma.sync.aligned.m16n8k16.row.col.f32.bf16.bf16.f32 "
                 "{%0,%1,%2,%3}, {%4,%5,%6,%7}, {%8,%9}, {%0,%1,%2,%3};"
                 : "+f"(c[0]), "+f"(c[1]), "+f"(c[2]), "+f"(c[3])
                 : "r"(a[0]), "r"(a[1]), "r"(a[2]), "r"(a[3]), "r"(b0), "r"(b1));
}
__device__ __forceinline__ uint32_t pkbf(float a, float b) {
    __nv_bfloat16 h0 = __float2bfloat16(a);
    __nv_bfloat16 h1 = __float2bfloat16(b);
    return (uint32_t)__bfloat16_as_ushort(h0) | ((uint32_t)__bfloat16_as_ushort(h1) << 16);
}

// ---------------------------------------------------------------------------
// Kernel 1: split-convert + transpose proj -> B[n][k] (K-major); tiny.
// ---------------------------------------------------------------------------
__global__ void convp_kernel(const float* __restrict__ proj) {
    int n = blockIdx.x, k = threadIdx.x;
    float v = proj[(size_t)k * N_PROJ + n];
    __nv_bfloat16 h = __float2bfloat16(v);
    __nv_bfloat16 l = __float2bfloat16(v - __bfloat162float(h));
    g_bhi[n * K_DIM + k] = h;
    g_blo[n * K_DIM + k] = l;
}

// ---------------------------------------------------------------------------
// Kernel 2: fused HMMA bf16-split GEMM, BM=64 BN=256 BK=32.
//   A: fp32 x loaded via LDG, split to bf16 hi/lo in-kernel, STS to SW128 smem.
//   B: pre-split bf16 via cp.async (L2-resident).
//   3 passes per K-chunk: Ah*Bh + Ah*Bl + Al*Bh, fp32 accum.
//   Epilogue writes transposed into g_xpt[g][p][i] (smem-staged, coalesced).
// ---------------------------------------------------------------------------
#define BM 64
#define BN 256
#define BK 32
#define GTHREADS 256
#define S_AOP   0        // aOp[2]: 64 rows x 128B = 8192 each
#define S_BOP   16384    // bOp[2]: 256 rows x 128B = 32768 each
#define GEMM_SMEM 81920
#define EPAD 68          // epilogue staging stride (floats)

__global__ void __launch_bounds__(GTHREADS, 2)
gemm_hmma_kernel(const float* __restrict__ x) {
    extern __shared__ char smem[];
    const uint32_t sb = smem_u32(smem);

    const int t     = threadIdx.x;
    const int lane  = t & 31;
    const int wid   = t >> 5;
    const int mBase = blockIdx.x * BM;
    const int wm    = (wid >> 2) * 32;   // warp tile 32 x 64
    const int wn    = (wid & 3) * 64;

    // ldmatrix per-lane geometry
    const int rsel  = lane & 15;
    const int khalf = lane >> 4;
    const int kx    = lane & 7;

    uint32_t mByte[2], nByte[4];
#pragma unroll
    for (int mi = 0; mi < 2; mi++) mByte[mi] = (uint32_t)(wm + mi * 16 + rsel) * 128;
#pragma unroll
    for (int ni = 0; ni < 4; ni++) nByte[ni] = (uint32_t)(wn + ni * 16 + rsel) * 128;

    // A LDG geometry: thread covers row = t>>2 (0..63), k-granule q = t&3 (8 floats)
    const int arow = t >> 2;
    const int aq   = t & 3;
    const float* aSrc = x + (size_t)(mBase + arow) * K_DIM + aq * 8;
    // producer swizzled STS offsets (hi granule aq, lo granule aq+4)
    const uint32_t swH = (uint32_t)(arow * 128 + ((aq)     ^ (arow & 7)) * 16);
    const uint32_t swL = (uint32_t)(arow * 128 + ((aq + 4) ^ (arow & 7)) * 16);

    float aF[8];
    auto ldgA = [&](int c) {
        const float4* p = (const float4*)(aSrc + c * BK);
        float4 u0 = p[0], u1 = p[1];
        aF[0] = u0.x; aF[1] = u0.y; aF[2] = u0.z; aF[3] = u0.w;
        aF[4] = u1.x; aF[5] = u1.y; aF[6] = u1.z; aF[7] = u1.w;
    };
    auto stsA = [&](int buf) {
        uint32_t h[4], l[4];
#pragma unroll
        for (int j = 0; j < 4; j++) {
            float f0 = aF[2 * j], f1 = aF[2 * j + 1];
            h[j] = pkbf(f0, f1);
            float r0 = f0 - __bfloat162float(__ushort_as_bfloat16((uint16_t)h[j]));
            float r1 = f1 - __bfloat162float(__ushort_as_bfloat16((uint16_t)(h[j] >> 16)));
            l[j] = pkbf(r0, r1);
        }
        char* base = smem + buf * 8192;
        *(uint4*)(base + swH) = make_uint4(h[0], h[1], h[2], h[3]);
        *(uint4*)(base + swL) = make_uint4(l[0], l[1], l[2], l[3]);
    };
    auto cpB = [&](int c) {
        const int kB = c * BK;
        const uint32_t bufB = sb + S_BOP + (c & 1) * 32768;
#pragma unroll
        for (int r = 0; r < 8; r++) {
            int u   = t + GTHREADS * r;          // 0..2047
            int row = u >> 3;
            int gg  = u & 7;                     // 0..3 hi, 4..7 lo
            uint32_t off = (uint32_t)(row * 128 + gg * 16);
            uint32_t sw  = off ^ ((off >> 3) & 0x70);
            const __nv_bfloat16* bsrc = (gg < 4 ? g_bhi : g_blo)
                                      + (size_t)row * K_DIM + kB + (gg & 3) * 8;
            cp_async16(bufB + sw, bsrc);
        }
        cp_commit();
    };

    float acc[2][8][4];
#pragma unroll
    for (int mi = 0; mi < 2; mi++)
#pragma unroll
        for (int ni = 0; ni < 8; ni++)
#pragma unroll
            for (int r = 0; r < 4; r++) acc[mi][ni][r] = 0.0f;

    // Prologue
    ldgA(0);
    cpB(0);
    cpB(1);
    stsA(0);
    ldgA(1);

    const int NCH = K_DIM / BK;   // 8
    for (int c = 0; c < NCH; c++) {
        if (c < NCH - 1) cp_wait1(); else cp_wait0();
        __syncthreads();

        // store A(c+1) (loaded last iteration), then prefetch A(c+2) into regs
        if (c + 1 < NCH) stsA((c + 1) & 1);
        if (c + 2 < NCH) ldgA(c + 2);

        const uint32_t bufA = sb + (c & 1) * 8192;
        const uint32_t bufB = sb + S_BOP + (c & 1) * 32768;

#pragma unroll
        for (int ks = 0; ks < 2; ks++) {
            const uint32_t segH = (uint32_t)((ks * 2 + khalf) ^ kx) << 4;
            const uint32_t segL = (uint32_t)((4 + ks * 2 + khalf) ^ kx) << 4;

            uint32_t ah[2][4], bh[4][4];
#pragma unroll
            for (int mi = 0; mi < 2; mi++)
                ldsm4(ah[mi][0], ah[mi][1], ah[mi][2], ah[mi][3], bufA + mByte[mi] + segH);
#pragma unroll
            for (int ni = 0; ni < 4; ni++)
                ldsm4(bh[ni][0], bh[ni][1], bh[ni][2], bh[ni][3], bufB + nByte[ni] + segH);

            // pass 1: Ah * Bh
#pragma unroll
            for (int mi = 0; mi < 2; mi++)
#pragma unroll
                for (int ni = 0; ni < 8; ni++)
                    mma_bf16(acc[mi][ni], ah[mi], bh[ni >> 1][ni & 1], bh[ni >> 1][(ni & 1) + 2]);

            // pass 2: Ah * Bl
            uint32_t bl[4][4];
#pragma unroll
            for (int ni = 0; ni < 4; ni++)
                ldsm4(bl[ni][0], bl[ni][1], bl[ni][2], bl[ni][3], bufB + nByte[ni] + segL);
#pragma unroll
            for (int mi = 0; mi < 2; mi++)
#pragma unroll
                for (int ni = 0; ni < 8; ni++)
                    mma_bf16(acc[mi][ni], bl[0][0] ? ah[mi] : ah[mi], bl[ni >> 1][ni & 1], bl[ni >> 1][(ni & 1) + 2]);

            // pass 3: Al * Bh
            uint32_t al[2][4];
#pragma unroll
            for (int mi = 0; mi < 2; mi++)
                ldsm4(al[mi][0], al[mi][1], al[mi][2], al[mi][3], bufA + mByte[mi] + segL);
#pragma unroll
            for (int mi = 0; mi < 2; mi++)
#pragma unroll
                for (int ni = 0; ni < 8; ni++)
                    mma_bf16(acc[mi][ni], al[mi], bh[ni >> 1][ni & 1], bh[ni >> 1][(ni & 1) + 2]);
        }

        __syncthreads();
        if (c + 2 < NCH) cpB(c + 2);
    }

    // Epilogue: stage D transposed in smem [n][m] (stride EPAD -> conflict-free)
    float* sOut = (float*)smem;
    const int crow = lane >> 2;
    const int ccol = (lane & 3) * 2;
#pragma unroll
    for (int mi = 0; mi < 2; mi++)
#pragma unroll
        for (int ni = 0; ni < 8; ni++) {
            int m0 = wm + mi * 16 + crow;
            int n0 = wn + ni * 8 + ccol;
            sOut[(n0    ) * EPAD + m0    ] = acc[mi][ni][0];
            sOut[(n0 + 1) * EPAD + m0    ] = acc[mi][ni][1];
            sOut[(n0    ) * EPAD + m0 + 8] = acc[mi][ni][2];
            sOut[(n0 + 1) * EPAD + m0 + 8] = acc[mi][ni][3];
        }
    __syncthreads();

    // Coalesced global write: g_xpt[(g*256 + n)*512 + i]
    const int g     = mBase >> 9;
    const int iBase = mBase & 511;
#pragma unroll
    for (int r = 0; r < 16; r++) {
        int u   = t + GTHREADS * r;          // 0..4095
        int row = u >> 4;                    // n 0..255
        int pos = u & 15;                    // float4 within 64 m
        float4 v = *(float4*)&sOut[row * EPAD + pos * 4];
        float* dst = g_xpt + ((size_t)(g * N_PROJ + row)) * NPG + iBase + pos * 4;
        *(float4*)dst = v;
    }
}

// ---------------------------------------------------------------------------
// Kernel 3: per-warp bitonic sort of 512 values + quantile gather + write
// ---------------------------------------------------------------------------
template<int KK, int J>
__device__ __forceinline__ void bstep(float (&v)[16], int lane) {
    if constexpr (J >= 16) {
#pragma unroll
        for (int r = 0; r < 16; r++) {
            float pv = __shfl_xor_sync(0xffffffffu, v[r], J >> 4);
            int i = lane * 16 + r;
            bool takeMin = ((i & KK) == 0) == ((i & J) == 0);
            v[r] = takeMin ? fminf(v[r], pv) : fmaxf(v[r], pv);
        }
    } else {
#pragma unroll
        for (int r = 0; r < 16; r++) {
            if ((r & J) == 0) {
                int i = lane * 16 + r;
                bool up = ((i & KK) == 0);
                float a = v[r], b = v[r | J];
                float mn = fminf(a, b), mx = fmaxf(a, b);
                v[r]     = up ? mn : mx;
                v[r | J] = up ? mx : mn;
            }
        }
    }
}
template<int KK, int J>
__device__ __forceinline__ void bmerge(float (&v)[16], int lane) {
    bstep<KK, J>(v, lane);
    if constexpr (J > 1) bmerge<KK, J / 2>(v, lane);
}

__global__ void __launch_bounds__(256)
sort_quant_kernel(const float* __restrict__ cw, float* __restrict__ out) {
    __shared__ float sbuf[8][512];      // sorted columns, one per warp
    __shared__ float qbuf[8][264];      // quantiles staged (padded stride)
    __shared__ int   qidx[NUM_Q];

    const int t = threadIdx.x;
    qidx[t] = (int)floorf(cw[t] * (float)(NPG - 1));   // matches jnp.floor(cw*511)
    __syncthreads();

    const int w    = t >> 5;
    const int lane = t & 31;
    const int col  = blockIdx.x * 8 + w;               // (g,p) column id

    float v[16];
    const float4* src = (const float4*)(g_xpt + (size_t)col * NPG);
#pragma unroll
    for (int q = 0; q < 4; q++) {
        float4 f = src[lane * 4 + q];
        v[q * 4 + 0] = f.x; v[q * 4 + 1] = f.y;
        v[q * 4 + 2] = f.z; v[q * 4 + 3] = f.w;
    }

    bmerge<2, 1>(v, lane);
    bmerge<4, 2>(v, lane);
    bmerge<8, 4>(v, lane);
    bmerge<16, 8>(v, lane);
    bmerge<32, 16>(v, lane);
    bmerge<64, 32>(v, lane);
    bmerge<128, 64>(v, lane);
    bmerge<256, 128>(v, lane);
    bmerge<512, 256>(v, lane);

    float4* dst = (float4*)sbuf[w];
#pragma unroll
    for (int q = 0; q < 4; q++)
        dst[lane * 4 + q] = make_float4(v[q * 4 + 0], v[q * 4 + 1], v[q * 4 + 2], v[q * 4 + 3]);
    __syncwarp();

#pragma unroll
    for (int s = 0; s < 8; s++) {
        int q = lane + 32 * s;
        qbuf[w][q] = sbuf[w][qidx[q]] * (1.0f / 256.0f);
    }
    __syncthreads();

    const int gg    = blockIdx.x >> 5;
    const int pbase = (blockIdx.x * 8) & 255;
    const size_t obase = (size_t)gg * (NUM_Q * N_PROJ) + pbase;
#pragma unroll
    for (int s = 0; s < 8; s++) {
        int e  = t + 256 * s;          // 0..2047
        int q  = e >> 3;
        int wp = e & 7;
        out[obase + (size_t)q * N_PROJ + wp] = qbuf[wp][q];
    }
}

// ---------------------------------------------------------------------------
// kernel_launch: convp -> fused HMMA gemm -> sort/quantile (graph-capturable)
// ---------------------------------------------------------------------------
extern "C" void kernel_launch(void* const* d_in, const int* in_sizes, int n_in,
                              void* d_out, int out_size) {
    const float* x    = (const float*)d_in[0];   // [131072, 256] f32
    const float* proj = (const float*)d_in[1];   // [256, 256]    f32
    const float* cw   = (const float*)d_in[2];   // [256]         f32
    float* out = (float*)d_out;                  // [256, 65536]  f32

    cudaFuncSetAttribute(gemm_hmma_kernel,
                         cudaFuncAttributeMaxDynamicSharedMemorySize,
                         GEMM_SMEM);

    convp_kernel<<<N_PROJ, K_DIM>>>(proj);
    gemm_hmma_kernel<<<M_NODES / BM, GTHREADS, GEMM_SMEM>>>(x);
    sort_quant_kernel<<<(NUM_G * N_PROJ) / 8, 256>>>(cw, out);
}